// round 2
// baseline (speedup 1.0000x reference)
#include <cuda_runtime.h>
#include <math.h>

#define NN 65536
#define KK 1024
#define DD 256

// Scratch (no allocation allowed anywhere)
__device__ float g_csq[KK];
__device__ int   g_idx[NN];
__device__ float g_counts[KK];
__device__ float g_sse;

// ---------- packed f32x2 helpers (sm_10x; ptxas never auto-fuses these) ----
__device__ __forceinline__ unsigned long long pk2(float lo, float hi) {
    unsigned long long r;
    asm("mov.b64 %0, {%1, %2};" : "=l"(r) : "f"(lo), "f"(hi));
    return r;
}
__device__ __forceinline__ void unpk2(unsigned long long v, float& lo, float& hi) {
    asm("mov.b64 {%0, %1}, %2;" : "=f"(lo), "=f"(hi) : "l"(v));
}
__device__ __forceinline__ void fma2(unsigned long long& acc,
                                     unsigned long long a,
                                     unsigned long long b) {
    asm("fma.rn.f32x2 %0, %1, %2, %0;" : "+l"(acc) : "l"(a), "l"(b));
}

__global__ void init_kernel() {
    int t = blockIdx.x * blockDim.x + threadIdx.x;
    if (t < KK) g_counts[t] = 0.f;
    if (t == 0) g_sse = 0.f;
}

// ||c_k||^2, one warp per codebook
__global__ void csq_kernel(const float* __restrict__ cb) {
    int warp = (blockIdx.x * blockDim.x + threadIdx.x) >> 5;
    int lane = threadIdx.x & 31;
    if (warp >= KK) return;
    const float* c = cb + (size_t)warp * DD;
    float s = 0.f;
    #pragma unroll
    for (int d = lane; d < DD; d += 32) { float v = c[d]; s += v * v; }
    #pragma unroll
    for (int o = 16; o; o >>= 1) s += __shfl_down_sync(0xffffffffu, s, o);
    if (lane == 0) g_csq[warp] = s;
}

// Main kernel: 128x128x8 SGEMM tiling, 8x8 micro-tile, packed f32x2 FMA,
// fused running argmin over score = ||c||^2 - 2*x.c (||x||^2 dropped).
// One block owns 128 input rows and scans all 1024 codebooks -> argmin stays
// block-local (no cross-block reduction).
__global__ __launch_bounds__(256) void argmin_kernel(
    const float* __restrict__ x,
    const float* __restrict__ cb,
    float* __restrict__ out_idx_f)
{
    __shared__ float As[8][132];   // [depth][row], padded: conflict-free + 16B-aligned rows
    __shared__ float Bs[8][132];   // [depth][col]
    __shared__ float s_val[128 * 16];
    __shared__ int   s_idx[128 * 16];

    const int tid = threadIdx.x;
    const int tx = tid & 15;            // column group: cols tx*8 .. tx*8+7
    const int ty = tid >> 4;            // row group:    rows ty*8 .. ty*8+7
    const int row_base = blockIdx.x * 128;

    const int lr = tid >> 1;            // 0..127 (gmem load row within tile)
    const int lc = (tid & 1) * 4;       // 0 or 4 (gmem load depth offset)

    float best_val[8];
    int   best_idx[8];
    #pragma unroll
    for (int i = 0; i < 8; ++i) { best_val[i] = 3.4e38f; best_idx[i] = 0; }

    for (int kt = 0; kt < KK / 128; ++kt) {
        unsigned long long acc2[4][8];          // row-pair i (2 rows), col j
        #pragma unroll
        for (int i = 0; i < 4; ++i)
            #pragma unroll
            for (int j = 0; j < 8; ++j) acc2[i][j] = 0ULL;  // (0.f, 0.f)

        for (int dc = 0; dc < DD / 8; ++dc) {
            const int d0 = dc * 8;
            float4 av = *(const float4*)(x  + (size_t)(row_base + lr)  * DD + d0 + lc);
            float4 bv = *(const float4*)(cb + (size_t)(kt * 128 + lr) * DD + d0 + lc);
            __syncthreads();   // previous tile fully consumed before overwrite
            As[lc + 0][lr] = av.x; As[lc + 1][lr] = av.y;
            As[lc + 2][lr] = av.z; As[lc + 3][lr] = av.w;
            Bs[lc + 0][lr] = bv.x; Bs[lc + 1][lr] = bv.y;
            Bs[lc + 2][lr] = bv.z; Bs[lc + 3][lr] = bv.w;
            __syncthreads();

            #pragma unroll
            for (int kk = 0; kk < 8; ++kk) {
                float4 a0 = *(const float4*)&As[kk][ty * 8];
                float4 a1 = *(const float4*)&As[kk][ty * 8 + 4];
                float4 b0 = *(const float4*)&Bs[kk][tx * 8];
                float4 b1 = *(const float4*)&Bs[kk][tx * 8 + 4];
                unsigned long long ap[4];
                ap[0] = pk2(a0.x, a0.y); ap[1] = pk2(a0.z, a0.w);
                ap[2] = pk2(a1.x, a1.y); ap[3] = pk2(a1.z, a1.w);
                float bf[8] = {b0.x, b0.y, b0.z, b0.w, b1.x, b1.y, b1.z, b1.w};
                #pragma unroll
                for (int j = 0; j < 8; ++j) {
                    unsigned long long bj = pk2(bf[j], bf[j]);
                    #pragma unroll
                    for (int i = 0; i < 4; ++i) fma2(acc2[i][j], ap[i], bj);
                }
            }
        }

        // Fold this column-tile into the running argmin. Columns visited in
        // ascending order with strict < keeps the lowest index on ties.
        const int colb = kt * 128 + tx * 8;
        #pragma unroll
        for (int j = 0; j < 8; ++j) {
            const float cq = g_csq[colb + j];
            const int col = colb + j;
            #pragma unroll
            for (int i = 0; i < 4; ++i) {
                float lo, hi;
                unpk2(acc2[i][j], lo, hi);
                float v0 = cq - 2.f * lo;
                float v1 = cq - 2.f * hi;
                if (v0 < best_val[2 * i])     { best_val[2 * i]     = v0; best_idx[2 * i]     = col; }
                if (v1 < best_val[2 * i + 1]) { best_val[2 * i + 1] = v1; best_idx[2 * i + 1] = col; }
            }
        }
    }

    // Cross-thread reduction: 16 column-threads per row.
    #pragma unroll
    for (int i = 0; i < 8; ++i) {
        s_val[(ty * 8 + i) * 16 + tx] = best_val[i];
        s_idx[(ty * 8 + i) * 16 + tx] = best_idx[i];
    }
    __syncthreads();
    if (tid < 128) {
        float bv = s_val[tid * 16];
        int   bi = s_idx[tid * 16];
        #pragma unroll
        for (int t = 1; t < 16; ++t) {
            float v  = s_val[tid * 16 + t];
            int   ix = s_idx[tid * 16 + t];
            if (v < bv || (v == bv && ix < bi)) { bv = v; bi = ix; }
        }
        g_idx[row_base + tid] = bi;
        out_idx_f[row_base + tid] = (float)bi;
    }
}

// Gather quantized rows + accumulate sum of squared error.
__global__ void gather_loss_kernel(const float* __restrict__ x,
                                   const float* __restrict__ cb,
                                   float* __restrict__ out) {
    __shared__ float red[256];
    float local = 0.f;
    const int total = NN * DD;
    for (int i = blockIdx.x * 256 + threadIdx.x; i < total; i += gridDim.x * 256) {
        int row = i >> 8;
        int d = i & (DD - 1);
        int idx = g_idx[row];
        float q = cb[(size_t)idx * DD + d];
        out[i] = q;
        float diff = x[i] - q;
        local += diff * diff;
    }
    red[threadIdx.x] = local;
    __syncthreads();
    #pragma unroll
    for (int o = 128; o; o >>= 1) {
        if (threadIdx.x < o) red[threadIdx.x] += red[threadIdx.x + o];
        __syncthreads();
    }
    if (threadIdx.x == 0) atomicAdd(&g_sse, red[0]);
}

// Histogram of assignments (shared-mem privatized).
__global__ void hist_kernel() {
    __shared__ float h[KK];
    for (int k = threadIdx.x; k < KK; k += 256) h[k] = 0.f;
    __syncthreads();
    for (int i = blockIdx.x * 256 + threadIdx.x; i < NN; i += gridDim.x * 256)
        atomicAdd(&h[g_idx[i]], 1.0f);
    __syncthreads();
    for (int k = threadIdx.x; k < KK; k += 256)
        if (h[k] != 0.f) atomicAdd(&g_counts[k], h[k]);
}

// loss + perplexity
__global__ void finalize_kernel(float* __restrict__ out) {
    __shared__ float red[KK];
    int k = threadIdx.x;
    float p = g_counts[k] * (1.0f / (float)NN);
    red[k] = p * logf(p + 1e-10f);
    __syncthreads();
    #pragma unroll
    for (int o = 512; o; o >>= 1) {
        if (k < o) red[k] += red[k + o];
        __syncthreads();
    }
    if (k == 0) {
        out[(size_t)NN * DD]     = g_sse / (float)((size_t)NN * DD);
        out[(size_t)NN * DD + 1] = expf(-red[0]);
    }
}

extern "C" void kernel_launch(void* const* d_in, const int* in_sizes, int n_in,
                              void* d_out, int out_size) {
    const float* x  = (const float*)d_in[0];
    const float* cb = (const float*)d_in[1];
    float* out = (float*)d_out;

    init_kernel<<<4, 256>>>();
    csq_kernel<<<(KK * 32 + 255) / 256, 256>>>(cb);
    argmin_kernel<<<NN / 128, 256>>>(x, cb, out + (size_t)NN * DD + 2);
    gather_loss_kernel<<<2048, 256>>>(x, cb, out);
    hist_kernel<<<64, 256>>>();
    finalize_kernel<<<1, KK>>>(out);
}